// round 7
// baseline (speedup 1.0000x reference)
#include <cuda_runtime.h>

// Per-pixel dynamic conv (KPN style), K=5. B=4, C=64, H=128, W=128.
// out[b,c,h,w] = sum_t core[b,t,c,h,w] * data_pad[b,c,h+t/5-2, w+t%5-2]
// Pure HBM stream: core = 419 MB read-once. Roofline floor ~59 us @ ~7.3 TB/s.
//
// R3 vs R2 (64.0us, DRAM 85.4%):
//  - 2 adjacent float4 outputs per thread -> 10 back-to-back core LDG.128
//    per di-row (deeper MLP, less DRAM idle), data row amortized over 8 cols.

#define KS 5
#define PAD 2

namespace {
constexpr int B = 4, C = 64, H = 128, W = 128;
constexpr int HW = H * W;
constexpr int CHW = C * HW;
constexpr int TAPS = KS * KS;
}

__global__ __launch_bounds__(256, 2)
void dynconv_kernel(const float* __restrict__ data,
                    const float* __restrict__ core,
                    float* __restrict__ out) {
    int idx = blockIdx.x * 256 + threadIdx.x;   // over B*C*H*(W/8) = 524288

    int w8 = idx & 15;              // 16 groups of 8 columns per row
    int h  = (idx >> 4) & (H - 1);
    int c  = (idx >> 11) & (C - 1);
    int b  = idx >> 17;
    int w0 = w8 << 3;               // first of 8 output columns

    const float* dbase = data + ((long)(b * C + c)) * HW;
    const float* cbase = core + ((long)(b * TAPS) * C + c) * HW + h * W + w0;

    float4 accA = make_float4(0.f, 0.f, 0.f, 0.f);   // cols w0..w0+3
    float4 accB = make_float4(0.f, 0.f, 0.f, 0.f);   // cols w0+4..w0+7

    #pragma unroll
    for (int di = 0; di < KS; di++) {
        int hh = h + di - PAD;
        const float* cp = cbase + (long)(di * KS) * CHW;

        // ---- front-batch: 10 independent streaming core loads ----
        float4 ca[KS], cb[KS];
        #pragma unroll
        for (int dj = 0; dj < KS; dj++) {
            ca[dj] = __ldcs(reinterpret_cast<const float4*>(cp + (long)dj * CHW));
            cb[dj] = __ldcs(reinterpret_cast<const float4*>(cp + (long)dj * CHW + 4));
        }

        // ---- data row (L1/L2 hits): 12 values w0-2 .. w0+9 ----
        float row[12];
        if (hh >= 0 && hh < H) {
            const float* dr = dbase + hh * W;
            #pragma unroll
            for (int k = 0; k < 12; k++) {
                int ww = w0 + k - PAD;
                row[k] = (ww >= 0 && ww < W) ? __ldg(dr + ww) : 0.f;
            }
        } else {
            #pragma unroll
            for (int k = 0; k < 12; k++) row[k] = 0.f;
        }

        // ---- consume: output col m of tap dj uses row[m + dj] ----
        #pragma unroll
        for (int dj = 0; dj < KS; dj++) {
            accA.x += ca[dj].x * row[dj + 0];
            accA.y += ca[dj].y * row[dj + 1];
            accA.z += ca[dj].z * row[dj + 2];
            accA.w += ca[dj].w * row[dj + 3];
            accB.x += cb[dj].x * row[dj + 4];
            accB.y += cb[dj].y * row[dj + 5];
            accB.z += cb[dj].z * row[dj + 6];
            accB.w += cb[dj].w * row[dj + 7];
        }
    }

    float* op = out + (long)idx * 8;
    *reinterpret_cast<float4*>(op)     = accA;
    *reinterpret_cast<float4*>(op + 4) = accB;
}

extern "C" void kernel_launch(void* const* d_in, const int* in_sizes, int n_in,
                              void* d_out, int out_size) {
    const float* data = (const float*)d_in[0];  // [4,64,128,128]
    const float* core = (const float*)d_in[1];  // [4,1600,128,128]
    float* out = (float*)d_out;                 // [4,64,128,128]

    int total8 = B * C * H * (W / 8);           // 524288
    dynconv_kernel<<<total8 / 256, 256>>>(data, core, out);
}

// round 9
// speedup vs baseline: 1.0325x; 1.0325x over previous
#include <cuda_runtime.h>

// Per-pixel dynamic conv (KPN style), K=5. B=4, C=64, H=128, W=128.
// out[b,c,h,w] = sum_t core[b,t,c,h,w] * data_pad[b,c,h+t/5-2, w+t%5-2]
// Pure HBM stream: core = 419 MB read-once.
//
// R4 vs R2 (64.0us, DRAM 85.4%, regs=64, occ 45%):
//  - keep R2's 4-outputs/thread shape (best L1 behavior)
//  - 2-stage software pipeline over di: preload next row's 5 core LDG.128
//    while consuming current -> 10 in flight/thread at occ 3 (24 warps/SM)
//  - __stcs on output (streaming write, don't pollute L2)
// R3 lesson: do NOT buy depth with occupancy (regs=128/occ=2 regressed).

#define KS 5
#define PAD 2

namespace {
constexpr int B = 4, C = 64, H = 128, W = 128;
constexpr int HW = H * W;
constexpr int CHW = C * HW;
constexpr int TAPS = KS * KS;
}

__global__ __launch_bounds__(256, 3)
void dynconv_kernel(const float* __restrict__ data,
                    const float* __restrict__ core,
                    float* __restrict__ out) {
    int idx = blockIdx.x * 256 + threadIdx.x;   // over B*C*H*(W/4) = 1048576

    int w4 = idx & 31;
    int h  = (idx >> 5) & (H - 1);
    int c  = (idx >> 12) & (C - 1);
    int b  = idx >> 18;
    int w0 = w4 << 2;

    const float* dbase = data + ((long)(b * C + c)) * HW;
    const float* cbase = core + ((long)(b * TAPS) * C + c) * HW + h * W + w0;

    float4 acc = make_float4(0.f, 0.f, 0.f, 0.f);

    // ---- pipeline prologue: preload di=0's 5 core vectors ----
    float4 cur[KS];
    #pragma unroll
    for (int dj = 0; dj < KS; dj++)
        cur[dj] = __ldcs(reinterpret_cast<const float4*>(cbase + (long)dj * CHW));

    #pragma unroll
    for (int di = 0; di < KS; di++) {
        // ---- preload next di row while current is in use ----
        float4 nxt[KS];
        if (di < KS - 1) {
            const float* cp = cbase + (long)((di + 1) * KS) * CHW;
            #pragma unroll
            for (int dj = 0; dj < KS; dj++)
                nxt[dj] = __ldcs(reinterpret_cast<const float4*>(cp + (long)dj * CHW));
        }

        // ---- data row (L1/L2 hits): 8 values w0-2 .. w0+5 ----
        int hh = h + di - PAD;
        float row[8];
        if (hh >= 0 && hh < H) {
            const float* dr = dbase + hh * W;
            #pragma unroll
            for (int k = 0; k < 8; k++) {
                int ww = w0 + k - PAD;
                row[k] = (ww >= 0 && ww < W) ? __ldg(dr + ww) : 0.f;
            }
        } else {
            #pragma unroll
            for (int k = 0; k < 8; k++) row[k] = 0.f;
        }

        // ---- consume current: output col m of tap dj uses row[m + dj] ----
        #pragma unroll
        for (int dj = 0; dj < KS; dj++) {
            acc.x += cur[dj].x * row[dj + 0];
            acc.y += cur[dj].y * row[dj + 1];
            acc.z += cur[dj].z * row[dj + 2];
            acc.w += cur[dj].w * row[dj + 3];
        }

        #pragma unroll
        for (int dj = 0; dj < KS; dj++) cur[dj] = nxt[dj];
    }

    __stcs(reinterpret_cast<float4*>(out + (long)idx * 4), acc);
}

extern "C" void kernel_launch(void* const* d_in, const int* in_sizes, int n_in,
                              void* d_out, int out_size) {
    const float* data = (const float*)d_in[0];  // [4,64,128,128]
    const float* core = (const float*)d_in[1];  // [4,1600,128,128]
    float* out = (float*)d_out;                 // [4,64,128,128]

    int total4 = B * C * H * (W / 4);           // 1048576
    dynconv_kernel<<<total4 / 256, 256>>>(data, core, out);
}